// round 1
// baseline (speedup 1.0000x reference)
#include <cuda_runtime.h>
#include <math.h>

#define Sn 128
#define Pn 32
#define HDn 32
#define EDn 16
#define GHn 72
#define GOn 8
#define MDn 64
#define Tn 8
#define Bn (Sn*Pn)
#define NT 512

struct Smem {
  __align__(16) float W2[2][GHn][GOn];   // exact stride 8 -> float4 loads
  float Wih[4*HDn][EDn+1];               // [128][17]
  float Whh[4*HDn][HDn+1];               // [128][33]
  float bg[4*HDn];
  float Wse[2][EDn];
  float bse[EDn];
  float Whp[HDn][2];
  float bhp[2];
  float W1bot[2][HDn][GHn+1];            // [2][32][73]
  float Wc[2][2][GHn];
  float c0[2][GHn];
  float Wm1[HDn+2*GOn][MDn];             // [48][64]
  float bm1[MDn];
  float Wm2[MDn][HDn+1];                 // [64][33]
  float bm2[HDn];
  float hid[Pn][HDn+1];
  float cc[Pn][HDn+1];
  float h2[Pn][HDn+1];
  float xv[Pn][EDn+1];
  float pos[Pn][2];
  float relp[Pn][2];
  int   gtmp[Pn];
  unsigned msk[2][Pn];
  float cinv[2][Pn];
  float u[Pn][GHn+1];                    // stride 73, conflict-free lane reads
  float qn[Pn][GHn+1];                   // stores -q
  float su[Pn][GHn+1];                   // pre-scaled by 1/cnt
  float Z[Pn*Pn][GOn+1];                 // stride 9
  float pooled[Pn][2*GOn];
  float mid[Pn][MDn+1];
};

static_assert(sizeof(Smem) <= 230000, "smem too big");

__device__ __forceinline__ float sigm(float x){
  return 1.0f/(1.0f + __expf(-x));
}
__device__ __forceinline__ float tanh_f(float x){
  float t = __expf(-2.0f*fabsf(x));
  float r = (1.0f - t)/(1.0f + t);
  return copysignf(r, x);
}

__global__ __launch_bounds__(NT, 1)
void dec_kernel(const float* __restrict__ last_pos, const float* __restrict__ last_pos_rel,
                const float* __restrict__ hh, const float* __restrict__ ch,
                const int* __restrict__ end_group,
                const float* __restrict__ W_se, const float* __restrict__ b_se,
                const float* __restrict__ Wih, const float* __restrict__ Whh,
                const float* __restrict__ bih, const float* __restrict__ bhh,
                const float* __restrict__ W_hp, const float* __restrict__ b_hp,
                const float* __restrict__ W_pse, const float* __restrict__ b_pse,
                const float* __restrict__ W1a, const float* __restrict__ W2a,
                const float* __restrict__ W1b, const float* __restrict__ W2b,
                const float* __restrict__ W_m1, const float* __restrict__ b_m1,
                const float* __restrict__ W_m2, const float* __restrict__ b_m2,
                float* __restrict__ out)
{
  extern __shared__ float smraw[];
  Smem& sm = *reinterpret_cast<Smem*>(smraw);
  const int tid  = threadIdx.x;
  const int base = blockIdx.x * Pn;

  // ---------------- load weights / state ----------------
  for (int i=tid;i<4*HDn*EDn;i+=NT) sm.Wih[i/EDn][i%EDn]=Wih[i];
  for (int i=tid;i<4*HDn*HDn;i+=NT) sm.Whh[i/HDn][i%HDn]=Whh[i];
  for (int i=tid;i<4*HDn;i+=NT)     sm.bg[i]=bih[i]+bhh[i];
  for (int i=tid;i<2*EDn;i+=NT)     sm.Wse[i/EDn][i%EDn]=W_se[i];
  for (int i=tid;i<EDn;i+=NT)       sm.bse[i]=b_se[i];
  for (int i=tid;i<HDn*2;i+=NT)     sm.Whp[i/2][i%2]=W_hp[i];
  for (int i=tid;i<2;i+=NT)         sm.bhp[i]=b_hp[i];
  for (int i=tid;i<2*HDn*GHn;i+=NT){
    int gi=i/(HDn*GHn); int r=(i/GHn)%HDn; int d=i%GHn;
    const float* W1 = gi? W1b : W1a;
    sm.W1bot[gi][r][d] = W1[(EDn+r)*GHn + d];
  }
  for (int i=tid;i<2*GHn;i+=NT){
    int gi=i/GHn; int d=i%GHn;
    const float* W1 = gi? W1b : W1a;
    float wc0=0.f, wc1=0.f, c00=0.f;
    #pragma unroll
    for (int k=0;k<EDn;k++){
      float w=W1[k*GHn+d];
      wc0 += W_pse[k]*w;
      wc1 += W_pse[EDn+k]*w;
      c00 += b_pse[k]*w;
    }
    sm.Wc[gi][0][d]=wc0; sm.Wc[gi][1][d]=wc1; sm.c0[gi][d]=c00;
  }
  for (int i=tid;i<2*GHn*GOn;i+=NT){
    int gi=i/(GHn*GOn); int r=(i/GOn)%GHn; int c=i%GOn;
    sm.W2[gi][r][c] = (gi? W2b : W2a)[r*GOn+c];
  }
  for (int i=tid;i<(HDn+2*GOn)*MDn;i+=NT) sm.Wm1[i/MDn][i%MDn]=W_m1[i];
  for (int i=tid;i<MDn;i+=NT)             sm.bm1[i]=b_m1[i];
  for (int i=tid;i<MDn*HDn;i+=NT)         sm.Wm2[i/HDn][i%HDn]=W_m2[i];
  for (int i=tid;i<HDn;i+=NT)             sm.bm2[i]=b_m2[i];
  for (int i=tid;i<Pn*HDn;i+=NT){ int p=i/HDn,h=i%HDn;
    sm.hid[p][h]=hh[(base+p)*HDn+h]; sm.cc[p][h]=ch[(base+p)*HDn+h]; }
  for (int i=tid;i<Pn*2;i+=NT) sm.pos[i/2][i%2]=last_pos[base*2+i];
  for (int i=tid;i<Pn*EDn;i+=NT){ int p=i/EDn,e=i%EDn;
    float r0=last_pos_rel[(base+p)*2], r1=last_pos_rel[(base+p)*2+1];
    sm.xv[p][e] = r0*W_se[e] + r1*W_se[EDn+e] + b_se[e]; }
  for (int i=tid;i<Pn;i+=NT) sm.gtmp[i]=end_group[base+i];
  __syncthreads();

  // group masks (fixed over time)
  if (tid < Pn){
    int gme = sm.gtmp[tid];
    unsigned ms=0u, md=0u;
    #pragma unroll
    for (int j=0;j<Pn;j++){
      bool samev = ((gme==sm.gtmp[j]) && (gme!=0)) || (j==tid);
      bool diffv = (!samev) || (j==tid);
      ms |= (samev?1u:0u) << j;
      md |= (diffv?1u:0u) << j;
    }
    sm.msk[0][tid]=ms; sm.msk[1][tid]=md;
    sm.cinv[0][tid]=1.0f/(float)__popc(ms);
    sm.cinv[1][tid]=1.0f/(float)__popc(md);
  }
  __syncthreads();

  // ---------------- time loop ----------------
  for (int t=0; t<Tn; t++){
    // ---- LSTM step: 1024 (ped,unit) items ----
    for (int id=tid; id<Pn*HDn; id+=NT){
      int p=id>>5, h=id&31;
      float ai=sm.bg[h], af=sm.bg[HDn+h], ag=sm.bg[2*HDn+h], ao=sm.bg[3*HDn+h];
      #pragma unroll
      for (int k=0;k<EDn;k++){
        float xv=sm.xv[p][k];
        ai=fmaf(xv,sm.Wih[h][k],ai);        af=fmaf(xv,sm.Wih[HDn+h][k],af);
        ag=fmaf(xv,sm.Wih[2*HDn+h][k],ag);  ao=fmaf(xv,sm.Wih[3*HDn+h][k],ao);
      }
      #pragma unroll
      for (int k=0;k<HDn;k++){
        float hv=sm.hid[p][k];
        ai=fmaf(hv,sm.Whh[h][k],ai);        af=fmaf(hv,sm.Whh[HDn+h][k],af);
        ag=fmaf(hv,sm.Whh[2*HDn+h][k],ag);  ao=fmaf(hv,sm.Whh[3*HDn+h][k],ao);
      }
      float cold = sm.cc[p][h];
      float c2 = sigm(af)*cold + sigm(ai)*tanh_f(ag);
      float h2v = sigm(ao)*tanh_f(c2);
      sm.cc[p][h]=c2; sm.h2[p][h]=h2v;
    }
    __syncthreads();

    // ---- rel_pos + pos update + output write ----
    for (int id=tid; id<Pn*2; id+=NT){
      int p=id>>1, d=id&1;
      float acc=sm.bhp[d];
      #pragma unroll
      for (int k=0;k<HDn;k++) acc=fmaf(sm.h2[p][k], sm.Whp[k][d], acc);
      sm.relp[p][d]=acc;
      sm.pos[p][d]+=acc;
      out[(size_t)((t*Bn + base + p)*2 + d)] = acc;
    }
    __syncthreads();

    // ---- pooling: two GCNs ----
    for (int gi=0; gi<2; gi++){
      // u[j] = pos_j@Wc + c0 + h2_j@W1bot ; qn[j] = -(pos_j@Wc)
      for (int id=tid; id<Pn*GHn; id+=NT){
        int j=id/GHn, d=id-j*GHn;
        float qv = sm.pos[j][0]*sm.Wc[gi][0][d] + sm.pos[j][1]*sm.Wc[gi][1][d];
        float uv = qv + sm.c0[gi][d];
        #pragma unroll
        for (int h=0;h<HDn;h++) uv = fmaf(sm.h2[j][h], sm.W1bot[gi][h][d], uv);
        sm.qn[j][d] = -qv;
        sm.u[j][d]  = uv;
      }
      __syncthreads();
      // su[i] = (sum_{k in mask(i)} u[k]) / cnt_i
      for (int id=tid; id<Pn*GHn; id+=NT){
        int i=id/GHn, d=id-i*GHn;
        unsigned m = sm.msk[gi][i];
        float acc=0.f;
        #pragma unroll
        for (int k=0;k<Pn;k++)
          acc += ((m>>k)&1u) ? sm.u[k][d] : 0.f;
        sm.su[i][d] = acc * sm.cinv[gi][i];
      }
      __syncthreads();
      // Z[i,j] = relu(layer1 combine) @ W2   (1024 pairs, warp lanes = j)
      for (int id=tid; id<Pn*Pn; id+=NT){
        int i=id>>5, j=id&31;
        unsigned mi = sm.msk[gi][i];
        bool diag = (i==j);
        bool sb = (mi>>j)&1u;
        const float* pA; const float* pB; float a0, a1;
        if (diag)      { pA=sm.su[i]; pB=sm.u[i]; a0=1.0f; a1=0.0f; }
        else if (sb)   { pA=sm.u[j];  pB=sm.u[i]; a0=0.5f; a1=0.5f; }
        else           { pA=sm.u[j];  pB=sm.u[i]; a0=1.0f; a1=0.0f; }
        const float* pq = sm.qn[i];
        const float4* w2b4 = reinterpret_cast<const float4*>(&sm.W2[gi][0][0]);
        float4 acc0 = make_float4(0.f,0.f,0.f,0.f);
        float4 acc1 = make_float4(0.f,0.f,0.f,0.f);
        #pragma unroll 4
        for (int d=0; d<GHn; d++){
          float h1 = fmaxf(fmaf(a0, pA[d], fmaf(a1, pB[d], pq[d])), 0.0f);
          float4 wA = w2b4[2*d], wB = w2b4[2*d+1];
          acc0.x=fmaf(h1,wA.x,acc0.x); acc0.y=fmaf(h1,wA.y,acc0.y);
          acc0.z=fmaf(h1,wA.z,acc0.z); acc0.w=fmaf(h1,wA.w,acc0.w);
          acc1.x=fmaf(h1,wB.x,acc1.x); acc1.y=fmaf(h1,wB.y,acc1.y);
          acc1.z=fmaf(h1,wB.z,acc1.z); acc1.w=fmaf(h1,wB.w,acc1.w);
        }
        float* zr = sm.Z[id];
        zr[0]=acc0.x; zr[1]=acc0.y; zr[2]=acc0.z; zr[3]=acc0.w;
        zr[4]=acc1.x; zr[5]=acc1.y; zr[6]=acc1.z; zr[7]=acc1.w;
      }
      __syncthreads();
      // layer-2 combine + relu + max over j  (256 items)
      for (int id=tid; id<Pn*GOn; id+=NT){
        int i=id>>3, c=id&7;
        unsigned mi = sm.msk[gi][i];
        float ci = sm.cinv[gi][i];
        const float* zrow = &sm.Z[i<<5][0];
        float zii = zrow[i*(GOn+1)+c];
        float sum = 0.f;
        float best = -3.4e38f;
        #pragma unroll
        for (int j=0;j<Pn;j++){
          float z = zrow[j*(GOn+1)+c];
          bool sb = (mi>>j)&1u;
          sum += sb ? z : 0.f;
          if (j!=i){
            float v = sb ? (z+zii)*0.5f : z;
            best = fmaxf(best, v);
          }
        }
        best = fmaxf(best, sum*ci);     // diag term
        sm.pooled[i][gi*GOn+c] = fmaxf(best, 0.0f);
      }
      __syncthreads();
    }

    // ---- MLP layer 1 ----
    for (int id=tid; id<Pn*MDn; id+=NT){
      int p=id>>6, m=id&63;
      float acc=sm.bm1[m];
      #pragma unroll
      for (int k=0;k<HDn;k++)   acc=fmaf(sm.h2[p][k],     sm.Wm1[k][m],      acc);
      #pragma unroll
      for (int k=0;k<2*GOn;k++) acc=fmaf(sm.pooled[p][k], sm.Wm1[HDn+k][m],  acc);
      sm.mid[p][m]=fmaxf(acc,0.0f);
    }
    __syncthreads();

    // ---- MLP layer 2 (new hidden) + next x ----
    for (int id=tid; id<Pn*HDn; id+=NT){
      int p=id>>5, h=id&31;
      float acc=sm.bm2[h];
      #pragma unroll
      for (int k=0;k<MDn;k++) acc=fmaf(sm.mid[p][k], sm.Wm2[k][h], acc);
      sm.hid[p][h]=fmaxf(acc,0.0f);
    }
    for (int id=tid; id<Pn*EDn; id+=NT){
      int p=id>>4, e=id&15;
      sm.xv[p][e] = fmaf(sm.relp[p][0], sm.Wse[0][e],
                    fmaf(sm.relp[p][1], sm.Wse[1][e], sm.bse[e]));
    }
    __syncthreads();
  }
}

extern "C" void kernel_launch(void* const* d_in, const int* in_sizes, int n_in,
                              void* d_out, int out_size)
{
  (void)in_sizes; (void)n_in; (void)out_size;
  const float* last_pos     = (const float*)d_in[0];
  const float* last_pos_rel = (const float*)d_in[1];
  const float* hh           = (const float*)d_in[2];
  const float* ch           = (const float*)d_in[3];
  /* d_in[4] = seq_start_end (int64) — scenes are uniform [s*P,(s+1)*P), unused */
  const int*   end_group    = (const int*)d_in[5];
  const float* W_se  = (const float*)d_in[6];
  const float* b_se  = (const float*)d_in[7];
  const float* Wih   = (const float*)d_in[8];
  const float* Whh   = (const float*)d_in[9];
  const float* bih   = (const float*)d_in[10];
  const float* bhh   = (const float*)d_in[11];
  const float* W_hp  = (const float*)d_in[12];
  const float* b_hp  = (const float*)d_in[13];
  const float* W_pse = (const float*)d_in[14];
  const float* b_pse = (const float*)d_in[15];
  const float* W1a   = (const float*)d_in[16];
  const float* W2a   = (const float*)d_in[17];
  const float* W1b   = (const float*)d_in[18];
  const float* W2b   = (const float*)d_in[19];
  const float* W_m1  = (const float*)d_in[20];
  const float* b_m1  = (const float*)d_in[21];
  const float* W_m2  = (const float*)d_in[22];
  const float* b_m2  = (const float*)d_in[23];
  float* out = (float*)d_out;

  cudaFuncSetAttribute(dec_kernel, cudaFuncAttributeMaxDynamicSharedMemorySize,
                       (int)sizeof(Smem));
  dec_kernel<<<Sn, NT, sizeof(Smem)>>>(
      last_pos, last_pos_rel, hh, ch, end_group,
      W_se, b_se, Wih, Whh, bih, bhh, W_hp, b_hp, W_pse, b_pse,
      W1a, W2a, W1b, W2b, W_m1, b_m1, W_m2, b_m2, out);
}

// round 2
// speedup vs baseline: 1.4393x; 1.4393x over previous
#include <cuda_runtime.h>
#include <math.h>

#define Sn 128
#define Pn 32
#define HDn 32
#define EDn 16
#define GHn 72
#define GOn 8
#define MDn 64
#define Tn 8
#define Bn (Sn*Pn)
#define NT 1024

typedef unsigned long long ull;

__device__ __forceinline__ ull pk2(float a, float b){
  ull r; asm("mov.b64 %0,{%1,%2};" : "=l"(r) : "f"(a), "f"(b)); return r;
}
__device__ __forceinline__ void upk2(ull v, float& a, float& b){
  asm("mov.b64 {%0,%1},%2;" : "=f"(a), "=f"(b) : "l"(v));
}
__device__ __forceinline__ ull fma2(ull a, ull b, ull c){
  ull r; asm("fma.rn.f32x2 %0,%1,%2,%3;" : "=l"(r) : "l"(a), "l"(b), "l"(c)); return r;
}
__device__ __forceinline__ ull lds64(const void* p){
  return *reinterpret_cast<const ull*>(p);
}

struct __align__(16) Smem {
  float W2[2][GHn][GOn];        // 4608B  rows 32B, ulonglong2-loadable
  float2 Wif2[48][HDn];         // 12288B  gates (i,f) packed, [k][h]
  float2 Wgo2[48][HDn];         // 12288B  gates (g,o)
  float2 bif2[HDn];             // 256B
  float2 bgo2[HDn];             // 256B
  float  Wse[2][EDn];           // 128B
  float  bse[EDn];              // 64B
  float2 Whp2[HDn];             // 256B
  float  bhp[2];                // 8B
  float2 W1b2[2][HDn][GHn/2];   // 18432B  [gi][h][dpair]
  float  Wc[2][2][GHn];         // 1152B
  float  c0[2][GHn];            // 576B
  float2 Wm12[48][MDn/2];       // 12288B  [k][mpair]
  float2 bm12[MDn/2];           // 256B
  float2 Wm22[MDn][HDn/2];      // 8192B  [k][hpair]
  float2 bm22[HDn/2];           // 128B
  float hid[Pn][HDn];           // 4096B
  float cc[Pn][HDn];            // 4096B
  float h2[Pn][HDn];            // 4096B
  float xv[Pn][EDn];            // 2048B
  float pos[Pn][2];             // 256B
  float relp[Pn][2];            // 256B
  int   gtmp[Pn];               // 128B
  unsigned msk[2][Pn];          // 256B
  float cinv[2][Pn];            // 256B
  unsigned gmask[8];            // 32B
  float u[2][Pn][GHn+1];        // 18688B  stride 73 (conflict-free lane-j)
  float su[2][Pn][GHn];         // 18432B
  float qn[2][Pn][GHn];         // 18432B  stores -q (broadcast reads only)
  float gsum[2][5][GHn];        // 2880B  [gi][0=total,1..4=group][d]
  float Z[2][Pn][296];          // 75776B  row j at j*9; i-stride 296 -> conflict-free max reads
  float pooled[Pn][2*GOn];      // 2048B
  float mid[Pn][MDn];           // 8192B
};
static_assert(sizeof(Smem) <= 232448, "smem too big");

__device__ __forceinline__ float sigm(float x){
  return 1.0f/(1.0f + __expf(-x));
}
__device__ __forceinline__ float tanh_f(float x){
  float t = __expf(-2.0f*fabsf(x));
  float r = (1.0f - t)/(1.0f + t);
  return copysignf(r, x);
}

__global__ __launch_bounds__(NT, 1)
void dec_kernel(const float* __restrict__ last_pos, const float* __restrict__ last_pos_rel,
                const float* __restrict__ hh, const float* __restrict__ ch,
                const int* __restrict__ end_group,
                const float* __restrict__ W_se, const float* __restrict__ b_se,
                const float* __restrict__ Wih, const float* __restrict__ Whh,
                const float* __restrict__ bih, const float* __restrict__ bhh,
                const float* __restrict__ W_hp, const float* __restrict__ b_hp,
                const float* __restrict__ W_pse, const float* __restrict__ b_pse,
                const float* __restrict__ W1a, const float* __restrict__ W2a,
                const float* __restrict__ W1b, const float* __restrict__ W2b,
                const float* __restrict__ W_m1, const float* __restrict__ b_m1,
                const float* __restrict__ W_m2, const float* __restrict__ b_m2,
                float* __restrict__ out)
{
  extern __shared__ float smraw[];
  Smem& sm = *reinterpret_cast<Smem*>(smraw);
  const int tid  = threadIdx.x;
  const int base = blockIdx.x * Pn;

  // ---------------- setup: weights (transposed/packed) + state ----------------
  for (int i=tid;i<48*HDn;i+=NT){
    int k=i>>5, h=i&31;
    float wi,wf,wg,wo;
    if (k<EDn){
      wi=Wih[h*EDn+k]; wf=Wih[(HDn+h)*EDn+k]; wg=Wih[(2*HDn+h)*EDn+k]; wo=Wih[(3*HDn+h)*EDn+k];
    } else {
      int kk=k-EDn;
      wi=Whh[h*HDn+kk]; wf=Whh[(HDn+h)*HDn+kk]; wg=Whh[(2*HDn+h)*HDn+kk]; wo=Whh[(3*HDn+h)*HDn+kk];
    }
    sm.Wif2[k][h]=make_float2(wi,wf); sm.Wgo2[k][h]=make_float2(wg,wo);
  }
  if (tid < HDn){
    int h=tid;
    sm.bif2[h]=make_float2(bih[h]+bhh[h], bih[HDn+h]+bhh[HDn+h]);
    sm.bgo2[h]=make_float2(bih[2*HDn+h]+bhh[2*HDn+h], bih[3*HDn+h]+bhh[3*HDn+h]);
    sm.Whp2[h]=make_float2(W_hp[h*2], W_hp[h*2+1]);
  }
  for (int i=tid;i<2*EDn;i+=NT) sm.Wse[i/EDn][i%EDn]=W_se[i];
  if (tid<EDn) sm.bse[tid]=b_se[tid];
  if (tid<2)   sm.bhp[tid]=b_hp[tid];
  for (int i=tid;i<2*HDn*(GHn/2);i+=NT){
    int gi=i/(HDn*36); int r=(i/36)%HDn; int dp=i%36;
    const float* W1 = gi? W1b : W1a;
    sm.W1b2[gi][r][dp]=make_float2(W1[(EDn+r)*GHn+2*dp], W1[(EDn+r)*GHn+2*dp+1]);
  }
  for (int i=tid;i<2*GHn;i+=NT){
    int gi=i/GHn; int d=i%GHn;
    const float* W1 = gi? W1b : W1a;
    float wc0=0.f, wc1=0.f, c00=0.f;
    #pragma unroll
    for (int k=0;k<EDn;k++){
      float w=W1[k*GHn+d];
      wc0 += W_pse[k]*w;
      wc1 += W_pse[EDn+k]*w;
      c00 += b_pse[k]*w;
    }
    sm.Wc[gi][0][d]=wc0; sm.Wc[gi][1][d]=wc1; sm.c0[gi][d]=c00;
  }
  for (int i=tid;i<2*GHn*GOn;i+=NT){
    int gi=i/(GHn*GOn); int r=(i/GOn)%GHn; int c=i%GOn;
    sm.W2[gi][r][c] = (gi? W2b : W2a)[r*GOn+c];
  }
  for (int i=tid;i<48*(MDn/2);i+=NT){
    int k=i/32, mp=i%32;
    sm.Wm12[k][mp]=make_float2(W_m1[k*MDn+2*mp], W_m1[k*MDn+2*mp+1]);
  }
  if (tid<MDn/2) sm.bm12[tid]=make_float2(b_m1[2*tid], b_m1[2*tid+1]);
  for (int i=tid;i<MDn*(HDn/2);i+=NT){
    int k=i/16, hp=i%16;
    sm.Wm22[k][hp]=make_float2(W_m2[k*HDn+2*hp], W_m2[k*HDn+2*hp+1]);
  }
  if (tid<HDn/2) sm.bm22[tid]=make_float2(b_m2[2*tid], b_m2[2*tid+1]);
  for (int i=tid;i<Pn*HDn;i+=NT){ int p=i>>5,h=i&31;
    sm.hid[p][h]=hh[(base+p)*HDn+h]; sm.cc[p][h]=ch[(base+p)*HDn+h]; }
  if (tid<Pn*2) sm.pos[tid>>1][tid&1]=last_pos[base*2+tid];
  for (int i=tid;i<Pn*EDn;i+=NT){ int p=i>>4,e=i&15;
    float r0=last_pos_rel[(base+p)*2], r1=last_pos_rel[(base+p)*2+1];
    sm.xv[p][e] = r0*W_se[e] + r1*W_se[EDn+e] + b_se[e]; }
  if (tid<Pn) sm.gtmp[tid]=end_group[base+tid];
  __syncthreads();

  if (tid < Pn){
    int gme = sm.gtmp[tid];
    unsigned ms=0u, md=0u;
    #pragma unroll
    for (int j=0;j<Pn;j++){
      bool samev = ((gme==sm.gtmp[j]) && (gme!=0)) || (j==tid);
      bool diffv = (!samev) || (j==tid);
      ms |= (samev?1u:0u) << j;
      md |= (diffv?1u:0u) << j;
    }
    sm.msk[0][tid]=ms; sm.msk[1][tid]=md;
    sm.cinv[0][tid]=1.0f/(float)__popc(ms);
    sm.cinv[1][tid]=1.0f/(float)__popc(md);
  }
  if (tid < 8){
    unsigned gm=0u;
    if (tid>=1 && tid<=4){
      for (int j=0;j<Pn;j++) if (sm.gtmp[j]==tid) gm |= 1u<<j;
    }
    sm.gmask[tid]=gm;
  }
  __syncthreads();

  const int lane = tid & 31;
  const int wp   = tid >> 5;

  // ---------------- time loop ----------------
  for (int t=0; t<Tn; t++){
    // ---- LSTM (warp = pedestrian, lane = hidden unit) + fused rel_pos ----
    {
      const int p=wp, h=lane;
      ull aif = lds64(&sm.bif2[h]);
      ull ago = lds64(&sm.bgo2[h]);
      #pragma unroll
      for (int k=0;k<EDn;k++){
        float v=sm.xv[p][k]; ull vv=pk2(v,v);
        aif=fma2(vv, lds64(&sm.Wif2[k][h]), aif);
        ago=fma2(vv, lds64(&sm.Wgo2[k][h]), ago);
      }
      #pragma unroll
      for (int k=0;k<HDn;k++){
        float v=sm.hid[p][k]; ull vv=pk2(v,v);
        aif=fma2(vv, lds64(&sm.Wif2[EDn+k][h]), aif);
        ago=fma2(vv, lds64(&sm.Wgo2[EDn+k][h]), ago);
      }
      float ai,af,ag,ao; upk2(aif,ai,af); upk2(ago,ag,ao);
      float cold = sm.cc[p][h];
      float c2 = sigm(af)*cold + sigm(ai)*tanh_f(ag);
      float h2v = sigm(ao)*tanh_f(c2);
      sm.cc[p][h]=c2; sm.h2[p][h]=h2v;
      // rel_pos via warp reduction
      float2 wph = sm.Whp2[h];
      float r0 = h2v*wph.x, r1 = h2v*wph.y;
      #pragma unroll
      for (int o=16;o;o>>=1){
        r0 += __shfl_xor_sync(0xFFFFFFFFu, r0, o);
        r1 += __shfl_xor_sync(0xFFFFFFFFu, r1, o);
      }
      if (lane==0){
        r0 += sm.bhp[0]; r1 += sm.bhp[1];
        sm.relp[p][0]=r0; sm.relp[p][1]=r1;
        sm.pos[p][0]+=r0; sm.pos[p][1]+=r1;
        *reinterpret_cast<float2*>(&out[(size_t)((t*Bn + base + p)*2)]) = make_float2(r0,r1);
      }
    }
    __syncthreads();

    // ---- u + qn (both gi): 2304 float2-items ----
    for (int id=tid; id<2*Pn*(GHn/2); id+=NT){
      int gi=id/1152; int r=id-gi*1152; int j=r/36, dp=r-j*36; int d0=2*dp;
      float x=sm.pos[j][0], y=sm.pos[j][1];
      float qa = x*sm.Wc[gi][0][d0]   + y*sm.Wc[gi][1][d0];
      float qb = x*sm.Wc[gi][0][d0+1] + y*sm.Wc[gi][1][d0+1];
      *reinterpret_cast<ull*>(&sm.qn[gi][j][d0]) = pk2(-qa,-qb);
      ull acc = pk2(qa + sm.c0[gi][d0], qb + sm.c0[gi][d0+1]);
      #pragma unroll
      for (int h=0;h<HDn;h++){
        float hv=sm.h2[j][h];
        acc = fma2(pk2(hv,hv), lds64(&sm.W1b2[gi][h][dp]), acc);
      }
      float ua,ub; upk2(acc,ua,ub);
      sm.u[gi][j][d0]=ua; sm.u[gi][j][d0+1]=ub;
    }
    __syncthreads();

    // ---- group sums: total + groups 1..4, per gi ----
    if (tid < 2*5*GHn){
      int gi=tid/360; int r=tid-gi*360; int s=r/GHn, d=r-s*GHn;
      unsigned m = (s==0) ? 0xFFFFFFFFu : sm.gmask[s];
      float acc=0.f;
      #pragma unroll
      for (int k=0;k<Pn;k++)
        acc += ((m>>k)&1u) ? sm.u[gi][k][d] : 0.f;
      sm.gsum[gi][s][d]=acc;
    }
    __syncthreads();

    // ---- su elementwise from group sums ----
    for (int id=tid; id<2*Pn*GHn; id+=NT){
      int gi=id/(Pn*GHn); int r=id-gi*Pn*GHn; int i=r/GHn, d=r-i*GHn;
      int g = sm.gtmp[i];
      float ui = sm.u[gi][i][d];
      float v;
      if (gi==0) v = g ? sm.gsum[0][g][d]*sm.cinv[0][i] : ui;
      else       v = g ? (sm.gsum[1][0][d]-sm.gsum[1][g][d]+ui)*sm.cinv[1][i]
                       :  sm.gsum[1][0][d]*sm.cinv[1][i];
      sm.su[gi][i][d]=v;
    }
    __syncthreads();

    // ---- Z: both gi, 2 pairs per thread (i and i+16, same j) ----
    {
      int j=tid&31, i1=(tid>>5)&15, gi=tid>>9, i2=i1+16;
      bool d1=(j==i1), s1=(sm.msk[gi][i1]>>j)&1u;
      bool d2=(j==i2), s2=(sm.msk[gi][i2]>>j)&1u;
      const float* pA1 = d1 ? &sm.su[gi][i1][0] : &sm.u[gi][j][0];
      const float* pA2 = d2 ? &sm.su[gi][i2][0] : &sm.u[gi][j][0];
      float a01=(s1&&!d1)?0.5f:1.0f, a11=(s1&&!d1)?0.5f:0.0f;
      float a02=(s2&&!d2)?0.5f:1.0f, a12=(s2&&!d2)?0.5f:0.0f;
      const float* pB1=&sm.u[gi][i1][0]; const float* pB2=&sm.u[gi][i2][0];
      const float* pq1=&sm.qn[gi][i1][0]; const float* pq2=&sm.qn[gi][i2][0];
      const ulonglong2* w2p = reinterpret_cast<const ulonglong2*>(&sm.W2[gi][0][0]);
      ull z10=0,z11=0,z12=0,z13=0, z20=0,z21=0,z22=0,z23=0;
      #pragma unroll 6
      for (int d=0; d<GHn; d++){
        float h1a = fmaxf(fmaf(a01, pA1[d], fmaf(a11, pB1[d], pq1[d])), 0.0f);
        float h1b = fmaxf(fmaf(a02, pA2[d], fmaf(a12, pB2[d], pq2[d])), 0.0f);
        ull hh1=pk2(h1a,h1a), hh2=pk2(h1b,h1b);
        ulonglong2 wA = w2p[2*d], wB = w2p[2*d+1];
        z10=fma2(hh1,wA.x,z10); z11=fma2(hh1,wA.y,z11);
        z12=fma2(hh1,wB.x,z12); z13=fma2(hh1,wB.y,z13);
        z20=fma2(hh2,wA.x,z20); z21=fma2(hh2,wA.y,z21);
        z22=fma2(hh2,wB.x,z22); z23=fma2(hh2,wB.y,z23);
      }
      float* zr1=&sm.Z[gi][i1][j*9];
      float* zr2=&sm.Z[gi][i2][j*9];
      float a,b;
      upk2(z10,a,b); zr1[0]=a; zr1[1]=b;  upk2(z11,a,b); zr1[2]=a; zr1[3]=b;
      upk2(z12,a,b); zr1[4]=a; zr1[5]=b;  upk2(z13,a,b); zr1[6]=a; zr1[7]=b;
      upk2(z20,a,b); zr2[0]=a; zr2[1]=b;  upk2(z21,a,b); zr2[2]=a; zr2[3]=b;
      upk2(z22,a,b); zr2[4]=a; zr2[5]=b;  upk2(z23,a,b); zr2[6]=a; zr2[7]=b;
    }
    __syncthreads();

    // ---- layer-2 combine + relu + max over j ----
    if (tid < 2*Pn*GOn){
      int gi=tid>>8, i=(tid>>3)&31, c=tid&7;
      const float* zrow = &sm.Z[gi][i][0];
      unsigned mi = sm.msk[gi][i];
      float zii = zrow[i*9+c];
      float sum = 0.f;
      float best = -3.4e38f;
      #pragma unroll
      for (int j=0;j<Pn;j++){
        float z = zrow[j*9+c];
        bool sb = (mi>>j)&1u;
        sum += sb ? z : 0.f;
        if (j!=i){
          float v = sb ? (z+zii)*0.5f : z;
          best = fmaxf(best, v);
        }
      }
      best = fmaxf(best, sum*sm.cinv[gi][i]);
      sm.pooled[i][gi*GOn+c] = fmaxf(best, 0.0f);
    }
    __syncthreads();

    // ---- MLP layer 1 (packed outputs) ----
    {
      int p=wp, mp=lane;
      ull acc = lds64(&sm.bm12[mp]);
      #pragma unroll
      for (int k=0;k<HDn;k++){
        float v=sm.h2[p][k];
        acc=fma2(pk2(v,v), lds64(&sm.Wm12[k][mp]), acc);
      }
      #pragma unroll
      for (int k=0;k<2*GOn;k++){
        float v=sm.pooled[p][k];
        acc=fma2(pk2(v,v), lds64(&sm.Wm12[HDn+k][mp]), acc);
      }
      float a,b; upk2(acc,a,b);
      *reinterpret_cast<ull*>(&sm.mid[p][2*mp]) = pk2(fmaxf(a,0.f), fmaxf(b,0.f));
    }
    __syncthreads();

    // ---- MLP layer 2 (new hidden) || next-x embedding ----
    if (tid < Pn*(HDn/2)){
      int p=tid>>4, hp=tid&15;
      ull acc = lds64(&sm.bm22[hp]);
      #pragma unroll
      for (int k=0;k<MDn;k++){
        float v=sm.mid[p][k];
        acc=fma2(pk2(v,v), lds64(&sm.Wm22[k][hp]), acc);
      }
      float a,b; upk2(acc,a,b);
      *reinterpret_cast<ull*>(&sm.hid[p][2*hp]) = pk2(fmaxf(a,0.f), fmaxf(b,0.f));
    } else if (tid < Pn*(HDn/2) + Pn*EDn){
      int id2 = tid - Pn*(HDn/2);
      int p=id2>>4, e=id2&15;
      sm.xv[p][e] = fmaf(sm.relp[p][0], sm.Wse[0][e],
                    fmaf(sm.relp[p][1], sm.Wse[1][e], sm.bse[e]));
    }
    __syncthreads();
  }
}

extern "C" void kernel_launch(void* const* d_in, const int* in_sizes, int n_in,
                              void* d_out, int out_size)
{
  (void)in_sizes; (void)n_in; (void)out_size;
  const float* last_pos     = (const float*)d_in[0];
  const float* last_pos_rel = (const float*)d_in[1];
  const float* hh           = (const float*)d_in[2];
  const float* ch           = (const float*)d_in[3];
  /* d_in[4] = seq_start_end (int64) — uniform scenes, unused */
  const int*   end_group    = (const int*)d_in[5];
  const float* W_se  = (const float*)d_in[6];
  const float* b_se  = (const float*)d_in[7];
  const float* Wih   = (const float*)d_in[8];
  const float* Whh   = (const float*)d_in[9];
  const float* bih   = (const float*)d_in[10];
  const float* bhh   = (const float*)d_in[11];
  const float* W_hp  = (const float*)d_in[12];
  const float* b_hp  = (const float*)d_in[13];
  const float* W_pse = (const float*)d_in[14];
  const float* b_pse = (const float*)d_in[15];
  const float* W1a   = (const float*)d_in[16];
  const float* W2a   = (const float*)d_in[17];
  const float* W1b   = (const float*)d_in[18];
  const float* W2b   = (const float*)d_in[19];
  const float* W_m1  = (const float*)d_in[20];
  const float* b_m1  = (const float*)d_in[21];
  const float* W_m2  = (const float*)d_in[22];
  const float* b_m2  = (const float*)d_in[23];
  float* out = (float*)d_out;

  cudaFuncSetAttribute(dec_kernel, cudaFuncAttributeMaxDynamicSharedMemorySize,
                       (int)sizeof(Smem));
  dec_kernel<<<Sn, NT, sizeof(Smem)>>>(
      last_pos, last_pos_rel, hh, ch, end_group,
      W_se, b_se, Wih, Whh, bih, bhh, W_hp, b_hp, W_pse, b_pse,
      W1a, W2a, W1b, W2b, W_m1, b_m1, W_m2, b_m2, out);
}

// round 3
// speedup vs baseline: 1.5918x; 1.1060x over previous
#include <cuda_runtime.h>
#include <math.h>

#define Sn 128
#define Pn 32
#define HDn 32
#define EDn 16
#define GHn 72
#define GOn 8
#define MDn 64
#define Tn 8
#define Bn (Sn*Pn)
#define NT 1024

typedef unsigned long long ull;

// ---- byte offsets into dynamic smem (all 16B aligned) ----
#define OFF_W2      0        // float [2][72][8]                 4608
#define OFF_WIF     4608     // float2 [32][50]  (i,f) T         12800
#define OFF_WGO     17408    // float2 [32][50]  (g,o) T         12800
#define OFF_BIF     30208    // float2 [32]                      256
#define OFF_BGO     30464    // float2 [32]                      256
#define OFF_WSE     30720    // float [2][16]                    128
#define OFF_BSE     30848    // float [16]                       64
#define OFF_WHP     30912    // float2 [32]                      256
#define OFF_BHP     31168    // float [2] (+pad)                 16
#define OFF_W1BT    31184    // float2 [2][36][34]               19584
#define OFF_WC      50768    // float2 [2][72]                   1152
#define OFF_C0      51920    // float [2][72]                    576
#define OFF_WM1T    52496    // float2 [32][50]                  12800
#define OFF_BM1     65296    // float2 [32]                      256
#define OFF_WM2     65552    // float2 [64][16]                  8192
#define OFF_BM2     73744    // float2 [16]                      128
#define OFF_H2      73872    // float [32][32]                   4096
#define OFF_POS     77968    // float [32][2] (+pad)             256
#define OFF_RELP    78224    // float [32][2] (+pad)             256
#define OFF_GTMP    78480    // int [32]                         128
#define OFF_MSK     78608    // unsigned [2][32]                 256
#define OFF_CINV    78864    // float [2][32]                    256
#define OFF_GMASK   79120    // unsigned [8] (+pad)              48
#define OFF_U       79168    // float [2][32][76]                19456
#define OFF_SU      98624    // float [2][32][72]                18432
#define OFF_MIXA    117056   // float2 [2][32][72]               36864
#define OFF_Z       153920   // float [2][32][296]               75776
#define SMEM_TOTAL  229696
// overlays (lifetime-disjoint):
#define OFF_HID     OFF_SU            // float [32][32]   4096
#define OFF_XV      (OFF_SU+4096)     // float [32][16]   2048
#define OFF_POOLED  OFF_U             // float [32][16]   2048
#define OFF_GSUM    OFF_Z             // float [2][5][72] 2880
#define OFF_MID     (OFF_Z+4096)      // float [32][64]   8192

#define USTR 76
#define ZSTR 296

__device__ __forceinline__ ull pk2(float a, float b){
  ull r; asm("mov.b64 %0,{%1,%2};" : "=l"(r) : "f"(a), "f"(b)); return r;
}
__device__ __forceinline__ void upk2(ull v, float& a, float& b){
  asm("mov.b64 {%0,%1},%2;" : "=f"(a), "=f"(b) : "l"(v));
}
__device__ __forceinline__ ull fma2(ull a, ull b, ull c){
  ull r; asm("fma.rn.f32x2 %0,%1,%2,%3;" : "=l"(r) : "l"(a), "l"(b), "l"(c)); return r;
}
__device__ __forceinline__ ull lds64(const void* p){ return *reinterpret_cast<const ull*>(p); }

__device__ __forceinline__ float sigm(float x){ return 1.0f/(1.0f + __expf(-x)); }
__device__ __forceinline__ float tanh_f(float x){
  float t = __expf(-2.0f*fabsf(x));
  float r = (1.0f - t)/(1.0f + t);
  return copysignf(r, x);
}

__global__ __launch_bounds__(NT, 1)
void dec_kernel(const float* __restrict__ last_pos, const float* __restrict__ last_pos_rel,
                const float* __restrict__ hh, const float* __restrict__ ch,
                const int* __restrict__ end_group,
                const float* __restrict__ W_se, const float* __restrict__ b_se,
                const float* __restrict__ Wih, const float* __restrict__ Whh,
                const float* __restrict__ bih, const float* __restrict__ bhh,
                const float* __restrict__ W_hp, const float* __restrict__ b_hp,
                const float* __restrict__ W_pse, const float* __restrict__ b_pse,
                const float* __restrict__ W1a, const float* __restrict__ W2a,
                const float* __restrict__ W1b, const float* __restrict__ W2b,
                const float* __restrict__ W_m1, const float* __restrict__ b_m1,
                const float* __restrict__ W_m2, const float* __restrict__ b_m2,
                float* __restrict__ out)
{
  extern __shared__ char smraw[];
  char* sb = smraw;
  float*    W2p   = (float*)   (sb+OFF_W2);
  float2*   WIF   = (float2*)  (sb+OFF_WIF);
  float2*   WGO   = (float2*)  (sb+OFF_WGO);
  float2*   BIF   = (float2*)  (sb+OFF_BIF);
  float2*   BGO   = (float2*)  (sb+OFF_BGO);
  float*    WSE   = (float*)   (sb+OFF_WSE);
  float*    BSE   = (float*)   (sb+OFF_BSE);
  float2*   WHP   = (float2*)  (sb+OFF_WHP);
  float*    BHP   = (float*)   (sb+OFF_BHP);
  float2*   W1BT  = (float2*)  (sb+OFF_W1BT);
  float2*   WC    = (float2*)  (sb+OFF_WC);
  float*    C0    = (float*)   (sb+OFF_C0);
  float2*   WM1T  = (float2*)  (sb+OFF_WM1T);
  float2*   BM1   = (float2*)  (sb+OFF_BM1);
  float2*   WM2   = (float2*)  (sb+OFF_WM2);
  float2*   BM2   = (float2*)  (sb+OFF_BM2);
  float*    H2    = (float*)   (sb+OFF_H2);
  float*    POS   = (float*)   (sb+OFF_POS);
  float*    RELP  = (float*)   (sb+OFF_RELP);
  int*      GTMP  = (int*)     (sb+OFF_GTMP);
  unsigned* MSK   = (unsigned*)(sb+OFF_MSK);
  float*    CINV  = (float*)   (sb+OFF_CINV);
  unsigned* GMASK = (unsigned*)(sb+OFF_GMASK);
  float*    U     = (float*)   (sb+OFF_U);
  float*    SU    = (float*)   (sb+OFF_SU);
  float2*   MIXA  = (float2*)  (sb+OFF_MIXA);
  float*    Zp    = (float*)   (sb+OFF_Z);
  float*    HID   = (float*)   (sb+OFF_HID);
  float*    XV    = (float*)   (sb+OFF_XV);
  float*    POOL  = (float*)   (sb+OFF_POOLED);
  float*    GSUM  = (float*)   (sb+OFF_GSUM);
  float*    MID   = (float*)   (sb+OFF_MID);

  const int tid  = threadIdx.x;
  const int base = blockIdx.x * Pn;
  const int lane = tid & 31;
  const int wp   = tid >> 5;

  // ---------------- setup ----------------
  for (int i=tid;i<2*GHn*GOn;i+=NT){
    int gi=i/(GHn*GOn); int rc=i%(GHn*GOn);
    W2p[i] = (gi? W2b : W2a)[rc];
  }
  for (int i=tid;i<HDn*48;i+=NT){
    int h=i/48, k=i%48;
    float wi,wf,wg,wo;
    if (k<EDn){
      wi=Wih[h*EDn+k]; wf=Wih[(HDn+h)*EDn+k]; wg=Wih[(2*HDn+h)*EDn+k]; wo=Wih[(3*HDn+h)*EDn+k];
    } else {
      int kk=k-EDn;
      wi=Whh[h*HDn+kk]; wf=Whh[(HDn+h)*HDn+kk]; wg=Whh[(2*HDn+h)*HDn+kk]; wo=Whh[(3*HDn+h)*HDn+kk];
    }
    WIF[h*50+k]=make_float2(wi,wf); WGO[h*50+k]=make_float2(wg,wo);
  }
  if (tid < HDn){
    int h=tid;
    BIF[h]=make_float2(bih[h]+bhh[h], bih[HDn+h]+bhh[HDn+h]);
    BGO[h]=make_float2(bih[2*HDn+h]+bhh[2*HDn+h], bih[3*HDn+h]+bhh[3*HDn+h]);
    WHP[h]=make_float2(W_hp[h*2], W_hp[h*2+1]);
  }
  for (int i=tid;i<2*EDn;i+=NT) WSE[i]=W_se[i];
  if (tid<EDn) BSE[tid]=b_se[tid];
  if (tid<2)   BHP[tid]=b_hp[tid];
  for (int i=tid;i<2*36*HDn;i+=NT){
    int gi=i/(36*HDn); int r=i%(36*HDn); int dp=r/HDn, h=r%HDn;
    const float* W1 = gi? W1b : W1a;
    W1BT[(gi*36+dp)*34+h]=make_float2(W1[(EDn+h)*GHn+2*dp], W1[(EDn+h)*GHn+2*dp+1]);
  }
  for (int i=tid;i<2*GHn;i+=NT){
    int gi=i/GHn; int d=i%GHn;
    const float* W1 = gi? W1b : W1a;
    float wc0=0.f, wc1=0.f, c00=0.f;
    #pragma unroll
    for (int k=0;k<EDn;k++){
      float w=W1[k*GHn+d];
      wc0 += W_pse[k]*w;
      wc1 += W_pse[EDn+k]*w;
      c00 += b_pse[k]*w;
    }
    WC[gi*GHn+d]=make_float2(wc0,wc1); C0[gi*GHn+d]=c00;
  }
  for (int i=tid;i<32*48;i+=NT){
    int mp=i/48, k=i%48;
    WM1T[mp*50+k]=make_float2(W_m1[k*MDn+2*mp], W_m1[k*MDn+2*mp+1]);
  }
  if (tid<MDn/2) BM1[tid]=make_float2(b_m1[2*tid], b_m1[2*tid+1]);
  for (int i=tid;i<MDn*16;i+=NT){
    int k=i/16, hp=i%16;
    WM2[k*16+hp]=make_float2(W_m2[k*HDn+2*hp], W_m2[k*HDn+2*hp+1]);
  }
  if (tid<16) BM2[tid]=make_float2(b_m2[2*tid], b_m2[2*tid+1]);
  for (int i=tid;i<Pn*HDn;i+=NT) HID[i]=hh[base*HDn+i];
  if (tid<Pn*2) POS[tid]=last_pos[base*2+tid];
  for (int i=tid;i<Pn*EDn;i+=NT){ int p=i>>4,e=i&15;
    float r0=last_pos_rel[(base+p)*2], r1=last_pos_rel[(base+p)*2+1];
    XV[p*EDn+e] = r0*W_se[e] + r1*W_se[EDn+e] + b_se[e]; }
  if (tid<Pn) GTMP[tid]=end_group[base+tid];
  float creg = ch[(base+wp)*HDn + lane];   // c-state lives in registers (warp=ped)
  __syncthreads();

  if (tid < Pn){
    int gme = GTMP[tid];
    unsigned ms=0u, md=0u;
    #pragma unroll
    for (int j=0;j<Pn;j++){
      bool samev = ((gme==GTMP[j]) && (gme!=0)) || (j==tid);
      bool diffv = (!samev) || (j==tid);
      ms |= (samev?1u:0u) << j;
      md |= (diffv?1u:0u) << j;
    }
    MSK[tid]=ms; MSK[Pn+tid]=md;
    CINV[tid]=1.0f/(float)__popc(ms);
    CINV[Pn+tid]=1.0f/(float)__popc(md);
  }
  if (tid < 8){
    unsigned gm=0u;
    if (tid>=1 && tid<=4){
      for (int j=0;j<Pn;j++) if (GTMP[j]==tid) gm |= 1u<<j;
    }
    GMASK[tid]=gm;
  }
  __syncthreads();

  // ---------------- time loop ----------------
  for (int t=0; t<Tn; t++){
    // ---- LSTM (warp=ped, lane=hidden unit) + fused rel_pos ----
    {
      const int p=wp, h=lane;
      const float2* wifr = WIF + h*50;
      const float2* wgor = WGO + h*50;
      ull aif = lds64(&BIF[h]);
      ull ago = lds64(&BGO[h]);
      #pragma unroll
      for (int k=0;k<EDn;k+=2){
        float2 v = *(const float2*)&XV[p*EDn+k];
        ulonglong2 wif = *(const ulonglong2*)&wifr[k];
        ulonglong2 wgo = *(const ulonglong2*)&wgor[k];
        ull v0=pk2(v.x,v.x), v1=pk2(v.y,v.y);
        aif=fma2(v0,wif.x,aif); aif=fma2(v1,wif.y,aif);
        ago=fma2(v0,wgo.x,ago); ago=fma2(v1,wgo.y,ago);
      }
      #pragma unroll
      for (int k=0;k<HDn;k+=2){
        float2 v = *(const float2*)&HID[p*HDn+k];
        ulonglong2 wif = *(const ulonglong2*)&wifr[EDn+k];
        ulonglong2 wgo = *(const ulonglong2*)&wgor[EDn+k];
        ull v0=pk2(v.x,v.x), v1=pk2(v.y,v.y);
        aif=fma2(v0,wif.x,aif); aif=fma2(v1,wif.y,aif);
        ago=fma2(v0,wgo.x,ago); ago=fma2(v1,wgo.y,ago);
      }
      float ai,af,ag,ao; upk2(aif,ai,af); upk2(ago,ag,ao);
      float c2 = sigm(af)*creg + sigm(ai)*tanh_f(ag);
      float h2v = sigm(ao)*tanh_f(c2);
      creg = c2;
      H2[p*HDn+h]=h2v;
      float2 wph = WHP[h];
      float r0 = h2v*wph.x, r1 = h2v*wph.y;
      #pragma unroll
      for (int o=16;o;o>>=1){
        r0 += __shfl_xor_sync(0xFFFFFFFFu, r0, o);
        r1 += __shfl_xor_sync(0xFFFFFFFFu, r1, o);
      }
      if (lane==0){
        r0 += BHP[0]; r1 += BHP[1];
        RELP[p*2]=r0; RELP[p*2+1]=r1;
        POS[p*2]+=r0; POS[p*2+1]+=r1;
        *reinterpret_cast<float2*>(&out[(size_t)((t*Bn + base + p)*2)]) = make_float2(r0,r1);
      }
    }
    __syncthreads();

    // ---- u (both gi): u[j][d] = pos_j@Wc + c0 + h2_j@W1bot ----
    for (int id=tid; id<2304; id+=NT){
      int gi=id/1152; int r=id-gi*1152; int j=r/36, dp=r-j*36;
      float2 ps = *(const float2*)&POS[j*2];
      float4 wc = *(const float4*)&WC[gi*GHn+2*dp];
      float2 cc0 = *(const float2*)&C0[gi*GHn+2*dp];
      ull acc = pk2(fmaf(ps.x,wc.x,fmaf(ps.y,wc.y,cc0.x)),
                    fmaf(ps.x,wc.z,fmaf(ps.y,wc.w,cc0.y)));
      const float2* wrow = W1BT + (gi*36+dp)*34;
      const float* h2row = H2 + j*HDn;
      #pragma unroll
      for (int h=0;h<HDn;h+=2){
        float2 v = *(const float2*)&h2row[h];
        ulonglong2 w = *(const ulonglong2*)&wrow[h];
        acc=fma2(pk2(v.x,v.x), w.x, acc);
        acc=fma2(pk2(v.y,v.y), w.y, acc);
      }
      *reinterpret_cast<ull*>(&U[(gi*Pn+j)*USTR + 2*dp]) = acc;
    }
    __syncthreads();

    // ---- group sums ----
    if (tid < 2*5*GHn){
      int gi=tid/360; int r=tid-gi*360; int s=r/GHn, d=r-s*GHn;
      unsigned m = (s==0) ? 0xFFFFFFFFu : GMASK[s];
      float acc=0.f;
      #pragma unroll
      for (int k=0;k<Pn;k++)
        acc += ((m>>k)&1u) ? U[(gi*Pn+k)*USTR+d] : 0.f;
      GSUM[gi*360 + s*GHn + d]=acc;
    }
    __syncthreads();

    // ---- mix: mixA = (-q_i, 0.5*u_i - q_i), su ----
    for (int id=tid; id<2*Pn*GHn; id+=NT){
      int gi=id/(Pn*GHn); int r=id-gi*Pn*GHn; int i=r/GHn, d=r-i*GHn;
      float2 wc = WC[gi*GHn+d];
      float q = POS[i*2]*wc.x + POS[i*2+1]*wc.y;
      float ui = U[(gi*Pn+i)*USTR+d];
      int g = GTMP[i];
      float tot = GSUM[gi*360+d];
      float gs = g ? GSUM[gi*360+g*GHn+d] : 0.f;
      float v;
      if (gi==0) v = g ? gs*CINV[i] : ui;
      else       v = g ? (tot-gs+ui)*CINV[Pn+i] : tot*CINV[Pn+i];
      SU[(gi*Pn+i)*GHn+d]=v;
      MIXA[(gi*Pn+i)*GHn+d]=make_float2(-q, fmaf(0.5f,ui,-q));
    }
    __syncthreads();

    // ---- Z: 2 pairs (i1, i2=i1+16) per thread, 4-d blocking ----
    {
      int j=lane, i1=(tid>>5)&15, gi=tid>>9, i2=i1+16;
      bool dg1=(j==i1), dg2=(j==i2);
      bool sel1 = (!dg1) && ((MSK[gi*Pn+i1]>>j)&1u);
      bool sel2 = (!dg2) && ((MSK[gi*Pn+i2]>>j)&1u);
      float cf1 = sel1?0.5f:1.0f, cf2 = sel2?0.5f:1.0f;
      const float4* pA1 = (const float4*)(dg1 ? &SU[(gi*Pn+i1)*GHn] : &U[(gi*Pn+j)*USTR]);
      const float4* pA2 = (const float4*)(dg2 ? &SU[(gi*Pn+i2)*GHn] : &U[(gi*Pn+j)*USTR]);
      const float2* pm1 = MIXA + (gi*Pn+i1)*GHn;
      const float2* pm2 = MIXA + (gi*Pn+i2)*GHn;
      const ulonglong2* w2p = (const ulonglong2*)(W2p + gi*GHn*GOn);
      ull z10=0,z11=0,z12=0,z13=0, z20=0,z21=0,z22=0,z23=0;
      #pragma unroll 2
      for (int db=0; db<GHn; db+=4){
        float4 a1 = pA1[db>>2];
        float4 a2 = pA2[db>>2];
        ulonglong2 mA = *(const ulonglong2*)(pm1+db);
        ulonglong2 mB = *(const ulonglong2*)(pm1+db+2);
        ulonglong2 nA = *(const ulonglong2*)(pm2+db);
        ulonglong2 nB = *(const ulonglong2*)(pm2+db+2);
        #pragma unroll
        for (int dd=0; dd<4; dd++){
          float ua = (&a1.x)[dd], ub = (&a2.x)[dd];
          float m0,m1; upk2(dd<2 ? (dd&1?mA.y:mA.x) : (dd&1?mB.y:mB.x), m0, m1);
          float n0,n1; upk2(dd<2 ? (dd&1?nA.y:nA.x) : (dd&1?nB.y:nB.x), n0, n1);
          float h1a = fmaxf(fmaf(cf1, ua, sel1?m1:m0), 0.0f);
          float h1b = fmaxf(fmaf(cf2, ub, sel2?n1:n0), 0.0f);
          ull hh1=pk2(h1a,h1a), hh2=pk2(h1b,h1b);
          ulonglong2 wA = w2p[2*(db+dd)], wB = w2p[2*(db+dd)+1];
          z10=fma2(hh1,wA.x,z10); z11=fma2(hh1,wA.y,z11);
          z12=fma2(hh1,wB.x,z12); z13=fma2(hh1,wB.y,z13);
          z20=fma2(hh2,wA.x,z20); z21=fma2(hh2,wA.y,z21);
          z22=fma2(hh2,wB.x,z22); z23=fma2(hh2,wB.y,z23);
        }
      }
      float* zr1=Zp + (gi*Pn+i1)*ZSTR + j*9;
      float* zr2=Zp + (gi*Pn+i2)*ZSTR + j*9;
      float a,b;
      upk2(z10,a,b); zr1[0]=a; zr1[1]=b;  upk2(z11,a,b); zr1[2]=a; zr1[3]=b;
      upk2(z12,a,b); zr1[4]=a; zr1[5]=b;  upk2(z13,a,b); zr1[6]=a; zr1[7]=b;
      upk2(z20,a,b); zr2[0]=a; zr2[1]=b;  upk2(z21,a,b); zr2[2]=a; zr2[3]=b;
      upk2(z22,a,b); zr2[4]=a; zr2[5]=b;  upk2(z23,a,b); zr2[6]=a; zr2[7]=b;
    }
    __syncthreads();

    // ---- layer-2 combine + relu + max over j ----
    if (tid < 2*Pn*GOn){
      int gi=tid>>8, i=(tid>>3)&31, c=tid&7;
      const float* zrow = Zp + (gi*Pn+i)*ZSTR;
      unsigned mi = MSK[gi*Pn+i];
      float zii = zrow[i*9+c];
      float sum = 0.f;
      float best = -3.4e38f;
      #pragma unroll
      for (int j=0;j<Pn;j++){
        float z = zrow[j*9+c];
        bool sbv = (mi>>j)&1u;
        sum += sbv ? z : 0.f;
        if (j!=i){
          float v = sbv ? (z+zii)*0.5f : z;
          best = fmaxf(best, v);
        }
      }
      best = fmaxf(best, sum*CINV[gi*Pn+i]);
      POOL[i*16 + gi*GOn + c] = fmaxf(best, 0.0f);
    }
    __syncthreads();

    // ---- MLP layer 1 ----
    {
      int p=wp, mp=lane;
      ull acc = lds64(&BM1[mp]);
      const float2* wrow = WM1T + mp*50;
      #pragma unroll
      for (int k=0;k<HDn;k+=2){
        float2 v = *(const float2*)&H2[p*HDn+k];
        ulonglong2 w = *(const ulonglong2*)&wrow[k];
        acc=fma2(pk2(v.x,v.x), w.x, acc);
        acc=fma2(pk2(v.y,v.y), w.y, acc);
      }
      #pragma unroll
      for (int k=0;k<2*GOn;k+=2){
        float2 v = *(const float2*)&POOL[p*16+k];
        ulonglong2 w = *(const ulonglong2*)&wrow[HDn+k];
        acc=fma2(pk2(v.x,v.x), w.x, acc);
        acc=fma2(pk2(v.y,v.y), w.y, acc);
      }
      float a,b; upk2(acc,a,b);
      *reinterpret_cast<ull*>(&MID[p*MDn+2*mp]) = pk2(fmaxf(a,0.f), fmaxf(b,0.f));
    }
    __syncthreads();

    // ---- MLP layer 2 (new hidden) || next-x embedding ----
    if (tid < 512){
      int p=tid>>4, hp=tid&15;
      ull acc = lds64(&BM2[hp]);
      #pragma unroll
      for (int k=0;k<MDn;k+=2){
        float2 v = *(const float2*)&MID[p*MDn+k];
        acc=fma2(pk2(v.x,v.x), lds64(&WM2[k*16+hp]), acc);
        acc=fma2(pk2(v.y,v.y), lds64(&WM2[(k+1)*16+hp]), acc);
      }
      float a,b; upk2(acc,a,b);
      *reinterpret_cast<ull*>(&HID[p*HDn+2*hp]) = pk2(fmaxf(a,0.f), fmaxf(b,0.f));
    } else {
      int id2 = tid - 512;
      int p=id2>>4, e=id2&15;
      XV[p*EDn+e] = fmaf(RELP[p*2], WSE[e],
                    fmaf(RELP[p*2+1], WSE[EDn+e], BSE[e]));
    }
    __syncthreads();
  }
}

extern "C" void kernel_launch(void* const* d_in, const int* in_sizes, int n_in,
                              void* d_out, int out_size)
{
  (void)in_sizes; (void)n_in; (void)out_size;
  const float* last_pos     = (const float*)d_in[0];
  const float* last_pos_rel = (const float*)d_in[1];
  const float* hh           = (const float*)d_in[2];
  const float* ch           = (const float*)d_in[3];
  /* d_in[4] = seq_start_end (int64) — uniform scenes, unused */
  const int*   end_group    = (const int*)d_in[5];
  const float* W_se  = (const float*)d_in[6];
  const float* b_se  = (const float*)d_in[7];
  const float* Wih   = (const float*)d_in[8];
  const float* Whh   = (const float*)d_in[9];
  const float* bih   = (const float*)d_in[10];
  const float* bhh   = (const float*)d_in[11];
  const float* W_hp  = (const float*)d_in[12];
  const float* b_hp  = (const float*)d_in[13];
  const float* W_pse = (const float*)d_in[14];
  const float* b_pse = (const float*)d_in[15];
  const float* W1a   = (const float*)d_in[16];
  const float* W2a   = (const float*)d_in[17];
  const float* W1b   = (const float*)d_in[18];
  const float* W2b   = (const float*)d_in[19];
  const float* W_m1  = (const float*)d_in[20];
  const float* b_m1  = (const float*)d_in[21];
  const float* W_m2  = (const float*)d_in[22];
  const float* b_m2  = (const float*)d_in[23];
  float* out = (float*)d_out;

  cudaFuncSetAttribute(dec_kernel, cudaFuncAttributeMaxDynamicSharedMemorySize, SMEM_TOTAL);
  dec_kernel<<<Sn, NT, SMEM_TOTAL>>>(
      last_pos, last_pos_rel, hh, ch, end_group,
      W_se, b_se, Wih, Whh, bih, bhh, W_hp, b_hp, W_pse, b_pse,
      W1a, W2a, W1b, W2b, W_m1, b_m1, W_m2, b_m2, out);
}

// round 4
// speedup vs baseline: 1.7056x; 1.0715x over previous
#include <cuda_runtime.h>
#include <math.h>

#define Sn 128
#define Pn 32
#define HDn 32
#define EDn 16
#define GHn 72
#define GOn 8
#define MDn 64
#define Tn 8
#define Bn (Sn*Pn)
#define NT 1024

typedef unsigned long long ull;

// ---- byte offsets into dynamic smem (16B aligned) ----
#define OFF_WL      0        // ulonglong2 [32][48]   24576  LSTM weights (h-major, broadcast)
#define OFF_BIF     24576    // ull [32]              256
#define OFF_BGO     24832    // ull [32]              256
#define OFF_WHP     25088    // float2 [32]           256
#define OFF_BHP     25344    // float [2]             16
#define OFF_WSE     25360    // float [32]            128
#define OFF_BSE     25488    // float [16]            64
#define OFF_W1BT    25552    // float2 [2*36][32]     18432
#define OFF_WCC     43984    // float2 [2][72]        1152
#define OFF_C0      45136    // float [2][72]         576
#define OFF_WM1P    45712    // ulonglong2 [32][24]   12288
#define OFF_BM1     58000    // ull [32]              256
#define OFF_WM2P    58256    // ulonglong2 [16][32]   8192
#define OFF_BM2     66448    // ull [16]              128
#define OFF_W2      66576    // float [2][72][8]      4608
#define OFF_H2T     71184    // float [32][33]        4224
#define OFF_HIDT    75408    // float [32][33]        4224
#define OFF_XVT     79632    // float [16][33]        2112
#define OFF_POS     81744    // float [2][32]         256
#define OFF_RELP    82000    // float [2][32]         256
#define OFF_PSUM    82256    // float [5][2]          64
#define OFF_GTMP    82320    // int [32]              128
#define OFF_MSK     82448    // unsigned [2][32]      256
#define OFF_CINV    82704    // float [2][32]         256
#define OFF_GMASK   82960    // unsigned [8]          48
#define OFF_U       83008    // float [2][32][76]     19456
#define OFF_Q       102464   // float [2][32][72]     18432  (-q)
#define OFF_SU      120896   // float [2][32][72]     18432
#define OFF_ZR      139328   // Z region              75776
#define SMEM_TOTAL  215104
// overlays (lifetime-disjoint):
#define OFF_UB      OFF_ZR            // float [2*72][33] 19008  (ubase, transposed; dead before Z writes)
#define OFF_GSUM    (OFF_ZR+19456)    // float [2][5][72] 2880   (gsum->mix; dead before Z writes)
#define OFF_MIDT    OFF_SU            // float [64][33]   8448   (MLP1->MLP2; SU dead after Z)
#define OFF_POOLT   (OFF_SU+8448)     // float [16][33]   2112   (max->MLP1)

#define USTR 76
#define ZSTR 296

__device__ __forceinline__ ull pk2(float a, float b){
  ull r; asm("mov.b64 %0,{%1,%2};" : "=l"(r) : "f"(a), "f"(b)); return r;
}
__device__ __forceinline__ void upk2(ull v, float& a, float& b){
  asm("mov.b64 {%0,%1},%2;" : "=f"(a), "=f"(b) : "l"(v));
}
__device__ __forceinline__ ull fma2(ull a, ull b, ull c){
  ull r; asm("fma.rn.f32x2 %0,%1,%2,%3;" : "=l"(r) : "l"(a), "l"(b), "l"(c)); return r;
}
__device__ __forceinline__ ull lds64(const void* p){ return *reinterpret_cast<const ull*>(p); }

__device__ __forceinline__ float sigm(float x){ return 1.0f/(1.0f + __expf(-x)); }
__device__ __forceinline__ float tanh_f(float x){
  float t = __expf(-2.0f*fabsf(x));
  float r = (1.0f - t)/(1.0f + t);
  return copysignf(r, x);
}

__global__ __launch_bounds__(NT, 1)
void dec_kernel(const float* __restrict__ last_pos, const float* __restrict__ last_pos_rel,
                const float* __restrict__ hh, const float* __restrict__ ch,
                const int* __restrict__ end_group,
                const float* __restrict__ W_se, const float* __restrict__ b_se,
                const float* __restrict__ Wih, const float* __restrict__ Whh,
                const float* __restrict__ bih, const float* __restrict__ bhh,
                const float* __restrict__ W_hp, const float* __restrict__ b_hp,
                const float* __restrict__ W_pse, const float* __restrict__ b_pse,
                const float* __restrict__ W1a, const float* __restrict__ W2a,
                const float* __restrict__ W1b, const float* __restrict__ W2b,
                const float* __restrict__ W_m1, const float* __restrict__ b_m1,
                const float* __restrict__ W_m2, const float* __restrict__ b_m2,
                float* __restrict__ out)
{
  extern __shared__ char sb[];
  ulonglong2* WL   = (ulonglong2*)(sb+OFF_WL);
  ull*      BIF    = (ull*)     (sb+OFF_BIF);
  ull*      BGO    = (ull*)     (sb+OFF_BGO);
  float2*   WHP    = (float2*)  (sb+OFF_WHP);
  float*    BHP    = (float*)   (sb+OFF_BHP);
  float*    WSE    = (float*)   (sb+OFF_WSE);
  float*    BSE    = (float*)   (sb+OFF_BSE);
  float2*   W1BT   = (float2*)  (sb+OFF_W1BT);
  float2*   WCC    = (float2*)  (sb+OFF_WCC);
  float*    C0     = (float*)   (sb+OFF_C0);
  ulonglong2* WM1P = (ulonglong2*)(sb+OFF_WM1P);
  ull*      BM1    = (ull*)     (sb+OFF_BM1);
  ulonglong2* WM2P = (ulonglong2*)(sb+OFF_WM2P);
  ull*      BM2    = (ull*)     (sb+OFF_BM2);
  float*    W2p    = (float*)   (sb+OFF_W2);
  float*    H2T    = (float*)   (sb+OFF_H2T);
  float*    HIDT   = (float*)   (sb+OFF_HIDT);
  float*    XVT    = (float*)   (sb+OFF_XVT);
  float*    POS    = (float*)   (sb+OFF_POS);
  float*    RELP   = (float*)   (sb+OFF_RELP);
  float*    PSUM   = (float*)   (sb+OFF_PSUM);
  int*      GTMP   = (int*)     (sb+OFF_GTMP);
  unsigned* MSK    = (unsigned*)(sb+OFF_MSK);
  float*    CINV   = (float*)   (sb+OFF_CINV);
  unsigned* GMASK  = (unsigned*)(sb+OFF_GMASK);
  float*    U      = (float*)   (sb+OFF_U);
  float*    Q      = (float*)   (sb+OFF_Q);
  float*    SU     = (float*)   (sb+OFF_SU);
  float*    ZR     = (float*)   (sb+OFF_ZR);
  float*    UB     = (float*)   (sb+OFF_UB);
  float*    GSUM   = (float*)   (sb+OFF_GSUM);
  float*    MIDT   = (float*)   (sb+OFF_MIDT);
  float*    POOLT  = (float*)   (sb+OFF_POOLT);

  const int tid  = threadIdx.x;
  const int base = blockIdx.x * Pn;
  const int lane = tid & 31;
  const int wp   = tid >> 5;

  // ---------------- setup ----------------
  // LSTM weights: WL[h][k] = {(wi,wf),(wg,wo)}
  for (int i=tid;i<HDn*48;i+=NT){
    int h=i/48, k=i%48;
    float wi,wf,wg,wo;
    if (k<EDn){
      wi=Wih[h*EDn+k]; wf=Wih[(HDn+h)*EDn+k]; wg=Wih[(2*HDn+h)*EDn+k]; wo=Wih[(3*HDn+h)*EDn+k];
    } else {
      int kk=k-EDn;
      wi=Whh[h*HDn+kk]; wf=Whh[(HDn+h)*HDn+kk]; wg=Whh[(2*HDn+h)*HDn+kk]; wo=Whh[(3*HDn+h)*HDn+kk];
    }
    ulonglong2 w; w.x=pk2(wi,wf); w.y=pk2(wg,wo);
    WL[i]=w;
  }
  if (tid < HDn){
    int h=tid;
    BIF[h]=pk2(bih[h]+bhh[h], bih[HDn+h]+bhh[HDn+h]);
    BGO[h]=pk2(bih[2*HDn+h]+bhh[2*HDn+h], bih[3*HDn+h]+bhh[3*HDn+h]);
    WHP[h]=make_float2(W_hp[h*2], W_hp[h*2+1]);
  }
  if (tid<2*EDn) WSE[tid]=W_se[tid];
  if (tid<EDn)   BSE[tid]=b_se[tid];
  if (tid<2)     BHP[tid]=b_hp[tid];
  // W1 bottom transposed: W1BT[(gi*36+dp)][h]
  for (int i=tid;i<2*36*HDn;i+=NT){
    int gi=i/(36*HDn); int r=i%(36*HDn); int dp=r/HDn, h=r%HDn;
    const float* W1 = gi? W1b : W1a;
    W1BT[(gi*36+dp)*32+h]=make_float2(W1[(EDn+h)*GHn+2*dp], W1[(EDn+h)*GHn+2*dp+1]);
  }
  for (int i=tid;i<2*GHn;i+=NT){
    int gi=i/GHn; int d=i%GHn;
    const float* W1 = gi? W1b : W1a;
    float wc0=0.f, wc1=0.f, c00=0.f;
    #pragma unroll
    for (int k=0;k<EDn;k++){
      float w=W1[k*GHn+d];
      wc0 += W_pse[k]*w;
      wc1 += W_pse[EDn+k]*w;
      c00 += b_pse[k]*w;
    }
    WCC[i]=make_float2(wc0,wc1); C0[i]=c00;
  }
  for (int i=tid;i<2*GHn*GOn;i+=NT){
    int gi=i/(GHn*GOn); int rc=i%(GHn*GOn);
    W2p[i] = (gi? W2b : W2a)[rc];
  }
  // MLP1 weights: WM1P[mp][k2]
  for (int i=tid;i<32*24;i+=NT){
    int mp=i/24, k2=i%24; int k0=2*k2;
    ulonglong2 w;
    w.x = pk2(W_m1[k0*MDn+2*mp],     W_m1[k0*MDn+2*mp+1]);
    w.y = pk2(W_m1[(k0+1)*MDn+2*mp], W_m1[(k0+1)*MDn+2*mp+1]);
    WM1P[i]=w;
  }
  if (tid<MDn/2) BM1[tid]=pk2(b_m1[2*tid], b_m1[2*tid+1]);
  // MLP2 weights: WM2P[hp][k2]
  for (int i=tid;i<16*32;i+=NT){
    int hp=i/32, k2=i%32; int k0=2*k2;
    ulonglong2 w;
    w.x = pk2(W_m2[k0*HDn+2*hp],     W_m2[k0*HDn+2*hp+1]);
    w.y = pk2(W_m2[(k0+1)*HDn+2*hp], W_m2[(k0+1)*HDn+2*hp+1]);
    WM2P[i]=w;
  }
  if (tid<16) BM2[tid]=pk2(b_m2[2*tid], b_m2[2*tid+1]);
  // state (transposed)
  for (int i=tid;i<Pn*HDn;i+=NT){ int p=i>>5, h=i&31; HIDT[h*33+p]=hh[base*HDn+i]; }
  for (int i=tid;i<Pn*EDn;i+=NT){ int p=i>>4, e=i&15;
    float r0=last_pos_rel[(base+p)*2], r1=last_pos_rel[(base+p)*2+1];
    XVT[e*33+p] = r0*W_se[e] + r1*W_se[EDn+e] + b_se[e]; }
  if (tid<64){ int dim=tid>>5, p=tid&31; POS[dim*32+p]=last_pos[(base+p)*2+dim]; }
  if (tid<Pn) GTMP[tid]=end_group[base+tid];
  // stage c-state (coalesced) through ZR scratch
  for (int i=tid;i<Pn*HDn;i+=NT) ZR[i]=ch[base*HDn+i];
  __syncthreads();

  float creg = ZR[lane*32 + wp];   // (p=lane, h=wp)
  if (tid < Pn){
    int gme = GTMP[tid];
    unsigned ms=0u, md=0u;
    #pragma unroll
    for (int j=0;j<Pn;j++){
      bool samev = ((gme==GTMP[j]) && (gme!=0)) || (j==tid);
      bool diffv = (!samev) || (j==tid);
      ms |= (samev?1u:0u) << j;
      md |= (diffv?1u:0u) << j;
    }
    MSK[tid]=ms; MSK[Pn+tid]=md;
    CINV[tid]=1.0f/(float)__popc(ms);
    CINV[Pn+tid]=1.0f/(float)__popc(md);
  }
  if (tid < 8){
    unsigned gm=0u;
    if (tid>=1 && tid<=4){
      for (int j=0;j<Pn;j++) if (GTMP[j]==tid) gm |= 1u<<j;
    }
    GMASK[tid]=gm;
  }
  __syncthreads();

  // ---------------- time loop ----------------
  for (int t=0; t<Tn; t++){
    // ---- LSTM: warp=h, lane=p; weights broadcast ----
    {
      const int h=wp, p=lane;
      const ulonglong2* wrow = WL + h*48;
      ull aif = BIF[h];
      ull ago = BGO[h];
      #pragma unroll
      for (int k=0;k<EDn;k++){
        ulonglong2 wv = wrow[k];
        float av = XVT[k*33+p];
        ull vv = pk2(av,av);
        aif=fma2(vv,wv.x,aif); ago=fma2(vv,wv.y,ago);
      }
      #pragma unroll
      for (int k=0;k<HDn;k++){
        ulonglong2 wv = wrow[EDn+k];
        float av = HIDT[k*33+p];
        ull vv = pk2(av,av);
        aif=fma2(vv,wv.x,aif); ago=fma2(vv,wv.y,ago);
      }
      float ai,af,ag,ao; upk2(aif,ai,af); upk2(ago,ag,ao);
      float c2 = sigm(af)*creg + sigm(ai)*tanh_f(ag);
      float h2v = sigm(ao)*tanh_f(c2);
      creg = c2;
      H2T[h*33+p]=h2v;
    }
    __syncthreads();

    // ---- ubase (warp=(gi,dp), lane=j) + relpos/pos/possum finalize (warps 30,31) ----
    for (int it = wp; it < 72; it += 32){
      int gi=it/36, dp=it%36, d0=2*dp;
      ull acc = pk2(C0[gi*GHn+d0], C0[gi*GHn+d0+1]);
      const float2* wrow = W1BT + (gi*36+dp)*32;
      #pragma unroll 8
      for (int h=0;h<HDn;h++){
        float av = H2T[h*33+lane];
        acc = fma2(pk2(av,av), lds64(&wrow[h]), acc);
      }
      float a,b; upk2(acc,a,b);
      UB[(gi*72+d0)*33 + lane] = a;
      UB[(gi*72+d0+1)*33 + lane] = b;
    }
    if (wp >= 30){
      int dim = wp - 30;
      float r = 0.f;
      #pragma unroll 8
      for (int h=0;h<HDn;h++){
        float2 wv = WHP[h];
        r = fmaf(H2T[h*33+lane], dim? wv.y : wv.x, r);
      }
      r += BHP[dim];
      float pn = POS[dim*32+lane] + r;
      POS[dim*32+lane] = pn;
      RELP[dim*32+lane] = r;
      out[((size_t)(t*Bn + base + lane))*2 + dim] = r;
      #pragma unroll
      for (int s=0;s<5;s++){
        unsigned m = s ? GMASK[s] : 0xFFFFFFFFu;
        float v = ((m>>lane)&1u) ? pn : 0.f;
        #pragma unroll
        for (int o=16;o;o>>=1) v += __shfl_xor_sync(0xFFFFFFFFu, v, o);
        if (lane==s) PSUM[s*2+dim]=v;
      }
    }
    __syncthreads();

    // ---- gsum: masked sums of u_full via ubase + analytic q-sums ----
    if (tid < 720){
      int gi=tid/360; int r=tid-gi*360; int s=r/GHn, d=r-s*GHn;
      unsigned m = s ? GMASK[s] : 0xFFFFFFFFu;
      const float* ubcol = UB + (gi*72+d)*33;
      float acc=0.f;
      #pragma unroll
      for (int k=0;k<Pn;k++)
        acc += ((m>>k)&1u) ? ubcol[k] : 0.f;
      float2 wc = WCC[gi*GHn+d];
      acc = fmaf(PSUM[s*2], wc.x, fmaf(PSUM[s*2+1], wc.y, acc));
      GSUM[gi*360 + s*GHn + d]=acc;
    }
    __syncthreads();

    // ---- mix: U = ubase + q, Q = -q, SU ----
    for (int id=tid; id<2304; id+=NT){
      int gi=id/1152; int r=id-gi*1152; int i=r/36, dp=r-i*36; int d0=2*dp;
      float ub0 = UB[(gi*72+d0)*33+i], ub1 = UB[(gi*72+d0+1)*33+i];
      float px = POS[i], py = POS[32+i];
      float4 wc = *(const float4*)&WCC[gi*GHn+d0];
      float q0 = px*wc.x + py*wc.y;
      float q1 = px*wc.z + py*wc.w;
      float u0 = ub0 + q0, u1 = ub1 + q1;
      *(ull*)&U[(gi*Pn+i)*USTR + d0] = pk2(u0,u1);
      *(ull*)&Q[(gi*Pn+i)*GHn + d0] = pk2(-q0,-q1);
      int g = GTMP[i];
      float ci = CINV[gi*Pn+i];
      float t0 = GSUM[gi*360+d0], t1 = GSUM[gi*360+d0+1];
      float gs0 = GSUM[gi*360+g*GHn+d0], gs1 = GSUM[gi*360+g*GHn+d0+1];
      float v0, v1;
      if (gi==0){ v0 = g? gs0*ci : u0;            v1 = g? gs1*ci : u1; }
      else      { v0 = g? (t0-gs0+u0)*ci : t0*ci; v1 = g? (t1-gs1+u1)*ci : t1*ci; }
      *(ull*)&SU[(gi*Pn+i)*GHn + d0] = pk2(v0,v1);
    }
    __syncthreads();

    // ---- Z: 2 pairs (i1, i2=i1+16) per thread ----
    {
      int j=lane, i1=(tid>>5)&15, gi=tid>>9, i2=i1+16;
      bool dg1=(j==i1), dg2=(j==i2);
      bool sel1 = (!dg1) && ((MSK[gi*Pn+i1]>>j)&1u);
      bool sel2 = (!dg2) && ((MSK[gi*Pn+i2]>>j)&1u);
      float cf1 = sel1?0.5f:1.0f, s1f = sel1?0.5f:0.0f;
      float cf2 = sel2?0.5f:1.0f, s2f = sel2?0.5f:0.0f;
      const float4* pu   = (const float4*)(U  + (gi*Pn+j )*USTR);
      const float4* psu1 = (const float4*)(SU + (gi*Pn+i1)*GHn);
      const float4* psu2 = (const float4*)(SU + (gi*Pn+i2)*GHn);
      const float2* pui1 = (const float2*)(U  + (gi*Pn+i1)*USTR);
      const float2* pui2 = (const float2*)(U  + (gi*Pn+i2)*USTR);
      const float2* pq1  = (const float2*)(Q  + (gi*Pn+i1)*GHn);
      const float2* pq2  = (const float2*)(Q  + (gi*Pn+i2)*GHn);
      const ulonglong2* w2p = (const ulonglong2*)(W2p + gi*GHn*GOn);
      ull z10=0,z11=0,z12=0,z13=0, z20=0,z21=0,z22=0,z23=0;
      #pragma unroll 2
      for (int db=0; db<18; db++){
        float4 a = pu[db];
        float4 a1 = a; if (dg1) a1 = psu1[db];
        float4 a2 = a; if (dg2) a2 = psu2[db];
        #pragma unroll
        for (int half=0; half<2; half++){
          float2 ui1 = pui1[db*2+half], ui2 = pui2[db*2+half];
          float2 q1  = pq1 [db*2+half], q2  = pq2 [db*2+half];
          #pragma unroll
          for (int dd=0; dd<2; dd++){
            int d = db*4 + half*2 + dd;
            float m1 = fmaf(s1f, dd? ui1.y:ui1.x, dd? q1.y:q1.x);
            float m2 = fmaf(s2f, dd? ui2.y:ui2.x, dd? q2.y:q2.x);
            float h1a = fmaxf(fmaf(cf1, (&a1.x)[half*2+dd], m1), 0.0f);
            float h1b = fmaxf(fmaf(cf2, (&a2.x)[half*2+dd], m2), 0.0f);
            ull hh1=pk2(h1a,h1a), hh2=pk2(h1b,h1b);
            ulonglong2 wA = w2p[2*d], wB = w2p[2*d+1];
            z10=fma2(hh1,wA.x,z10); z11=fma2(hh1,wA.y,z11);
            z12=fma2(hh1,wB.x,z12); z13=fma2(hh1,wB.y,z13);
            z20=fma2(hh2,wA.x,z20); z21=fma2(hh2,wA.y,z21);
            z22=fma2(hh2,wB.x,z22); z23=fma2(hh2,wB.y,z23);
          }
        }
      }
      float* zr1=ZR + (gi*Pn+i1)*ZSTR + j*9;
      float* zr2=ZR + (gi*Pn+i2)*ZSTR + j*9;
      float a,b;
      upk2(z10,a,b); zr1[0]=a; zr1[1]=b;  upk2(z11,a,b); zr1[2]=a; zr1[3]=b;
      upk2(z12,a,b); zr1[4]=a; zr1[5]=b;  upk2(z13,a,b); zr1[6]=a; zr1[7]=b;
      upk2(z20,a,b); zr2[0]=a; zr2[1]=b;  upk2(z21,a,b); zr2[2]=a; zr2[3]=b;
      upk2(z22,a,b); zr2[4]=a; zr2[5]=b;  upk2(z23,a,b); zr2[6]=a; zr2[7]=b;
    }
    __syncthreads();

    // ---- layer-2 combine + relu + max over j ----
    if (tid < 512){
      int gi=tid>>8, i=(tid>>3)&31, c=tid&7;
      const float* zrow = ZR + (gi*Pn+i)*ZSTR;
      unsigned mi = MSK[gi*Pn+i];
      float zii = zrow[i*9+c];
      float sum = 0.f;
      float best = -3.4e38f;
      #pragma unroll
      for (int j=0;j<Pn;j++){
        float z = zrow[j*9+c];
        bool sbv = (mi>>j)&1u;
        sum += sbv ? z : 0.f;
        if (j!=i){
          float v = sbv ? (z+zii)*0.5f : z;
          best = fmaxf(best, v);
        }
      }
      best = fmaxf(best, sum*CINV[gi*Pn+i]);
      POOLT[(gi*GOn+c)*33 + i] = fmaxf(best, 0.0f);
    }
    __syncthreads();

    // ---- MLP layer 1: warp=mp, lane=p ----
    {
      int mp=wp, p=lane;
      ull acc = BM1[mp];
      const ulonglong2* wrow = WM1P + mp*24;
      #pragma unroll
      for (int k2=0;k2<16;k2++){
        ulonglong2 w = wrow[k2];
        float a0 = H2T[(2*k2)*33+p], a1 = H2T[(2*k2+1)*33+p];
        acc=fma2(pk2(a0,a0), w.x, acc);
        acc=fma2(pk2(a1,a1), w.y, acc);
      }
      #pragma unroll
      for (int k2=16;k2<24;k2++){
        ulonglong2 w = wrow[k2];
        float a0 = POOLT[(2*k2-32)*33+p], a1 = POOLT[(2*k2-31)*33+p];
        acc=fma2(pk2(a0,a0), w.x, acc);
        acc=fma2(pk2(a1,a1), w.y, acc);
      }
      float a,b; upk2(acc,a,b);
      MIDT[(2*mp)*33+p]=fmaxf(a,0.f);
      MIDT[(2*mp+1)*33+p]=fmaxf(b,0.f);
    }
    __syncthreads();

    // ---- MLP layer 2 (warps 0-15) || next-x embedding (warps 16-31) ----
    if (wp < 16){
      int hp=wp, p=lane;
      ull acc = BM2[hp];
      const ulonglong2* wrow = WM2P + hp*32;
      #pragma unroll 8
      for (int k2=0;k2<32;k2++){
        ulonglong2 w = wrow[k2];
        float a0 = MIDT[(2*k2)*33+p], a1 = MIDT[(2*k2+1)*33+p];
        acc=fma2(pk2(a0,a0), w.x, acc);
        acc=fma2(pk2(a1,a1), w.y, acc);
      }
      float a,b; upk2(acc,a,b);
      HIDT[(2*hp)*33+p]=fmaxf(a,0.f);
      HIDT[(2*hp+1)*33+p]=fmaxf(b,0.f);
    } else {
      int e = wp-16, p = lane;
      XVT[e*33+p] = fmaf(RELP[p], WSE[e],
                    fmaf(RELP[32+p], WSE[EDn+e], BSE[e]));
    }
    __syncthreads();
  }
}

extern "C" void kernel_launch(void* const* d_in, const int* in_sizes, int n_in,
                              void* d_out, int out_size)
{
  (void)in_sizes; (void)n_in; (void)out_size;
  const float* last_pos     = (const float*)d_in[0];
  const float* last_pos_rel = (const float*)d_in[1];
  const float* hh           = (const float*)d_in[2];
  const float* ch           = (const float*)d_in[3];
  /* d_in[4] = seq_start_end (int64) — uniform scenes, unused */
  const int*   end_group    = (const int*)d_in[5];
  const float* W_se  = (const float*)d_in[6];
  const float* b_se  = (const float*)d_in[7];
  const float* Wih   = (const float*)d_in[8];
  const float* Whh   = (const float*)d_in[9];
  const float* bih   = (const float*)d_in[10];
  const float* bhh   = (const float*)d_in[11];
  const float* W_hp  = (const float*)d_in[12];
  const float* b_hp  = (const float*)d_in[13];
  const float* W_pse = (const float*)d_in[14];
  const float* b_pse = (const float*)d_in[15];
  const float* W1a   = (const float*)d_in[16];
  const float* W2a   = (const float*)d_in[17];
  const float* W1b   = (const float*)d_in[18];
  const float* W2b   = (const float*)d_in[19];
  const float* W_m1  = (const float*)d_in[20];
  const float* b_m1  = (const float*)d_in[21];
  const float* W_m2  = (const float*)d_in[22];
  const float* b_m2  = (const float*)d_in[23];
  float* out = (float*)d_out;

  cudaFuncSetAttribute(dec_kernel, cudaFuncAttributeMaxDynamicSharedMemorySize, SMEM_TOTAL);
  dec_kernel<<<Sn, NT, SMEM_TOTAL>>>(
      last_pos, last_pos_rel, hh, ch, end_group,
      W_se, b_se, Wih, Whh, bih, bhh, W_hp, b_hp, W_pse, b_pse,
      W1a, W2a, W1b, W2b, W_m1, b_m1, W_m2, b_m2, out);
}